// round 4
// baseline (speedup 1.0000x reference)
#include <cuda_runtime.h>
#include <cuda_bf16.h>
#include <math.h>

#define B   64
#define NT  20000
#define NT1 20001
#define H4  1024
#define HD  256
#define Y_SZ    (B*NT1)
#define ENC_OFF Y_SZ
#define DEC_OFF (Y_SZ + B*HD)

#define RC  40      // row-chunks for sparse GEMM1 (500 rows each)
#define RPB 500
#define GRP 20

// ---------------- scratch (device globals; no allocations) -----------------
__device__ float g_counts[NT*B];                 // [tag][batch]
__device__ int   g_isum[B], g_isq[B];
__device__ float g_mu[B], g_rstd[B];
__device__ float g_pacc[4*B*NT1];                // GEMM1 partials (RC*B*H4) & dec split-K partials
__device__ float g_psgw[RC*H4], g_psbw[RC*H4];
__device__ float g_sgw[H4], g_sbw[H4];
__device__ float g_h1[B*H4], g_h2[B*H4], g_h3[B*H4], g_encb[B*HD], g_dd[B*H4];
__device__ float g_pbuf[8*B*H4];                 // small-GEMM split-K partials

__device__ __forceinline__ float gelu_exact(float x){
    return 0.5f * x * (1.0f + erff(x * 0.70710678118654752f));
}

// ---------------- K0: zero scratch -----------------------------------------
__global__ void k0_zero(){
    int i = blockIdx.x*256 + threadIdx.x;
    for (int idx = i; idx < NT*B; idx += 640*256) g_counts[idx] = 0.0f;
    if (i < B){ g_isum[i] = 0; g_isq[i] = 0; }
}

// ---------------- K1: scatter multi-hot counts ------------------------------
__global__ void k1_scatter(const int* __restrict__ tags){
    int p = blockIdx.x*256 + threadIdx.x;       // (b,f) pair, 8192 total
    if (p >= B*128) return;
    int b = p >> 7;
    const int* t = tags + p*16;
    int v[16];
    #pragma unroll
    for (int i = 0; i < 16; i++) v[i] = t[i];
    #pragma unroll
    for (int i = 0; i < 16; i++){
        bool dup = false;
        #pragma unroll
        for (int s = 0; s < 16; s++) if (s < i) dup = dup || (v[s] == v[i]);
        if (!dup) atomicAdd(&g_counts[v[i]*B + b], 1.0f);
    }
}

// ---------------- K2: per-batch stats (integer-exact, deterministic) --------
__global__ void k2a_stats(){
    int tid = threadIdx.x;
    int b = tid & 63;
    int s = 0, sq = 0;
    for (int idx = blockIdx.x*256 + tid; idx < NT*B; idx += 160*256){
        int c = __float2int_rn(g_counts[idx]);
        s += c; sq += c*c;
    }
    atomicAdd(&g_isum[b], s);
    atomicAdd(&g_isq[b], sq);
}
__global__ void k2b_fin(){
    int b = threadIdx.x;
    if (b >= B) return;
    float mu  = (float)g_isum[b] / (float)NT;
    float var = (float)g_isq[b] / (float)NT - mu*mu;
    g_mu[b] = mu;
    g_rstd[b] = rsqrtf(var + 1e-5f);
}

// ---------------- K3: write y (output #1) via smem transpose ----------------
__global__ void __launch_bounds__(256) k3_y(const float* __restrict__ fc,
                                            const float* __restrict__ lng,
                                            const float* __restrict__ lnb,
                                            float* __restrict__ y){
    __shared__ float t[64*65];
    int tid = threadIdx.x;
    int j0 = blockIdx.x * 64;
    #pragma unroll
    for (int i = 0; i < 16; i++){
        int idx = i*256 + tid; int r = idx >> 6, b = idx & 63; int j = j0 + r;
        t[r*65 + b] = (j < NT) ? g_counts[j*B + b] : 0.0f;
    }
    __syncthreads();
    #pragma unroll
    for (int i = 0; i < 16; i++){
        int idx = i*256 + tid; int b = idx >> 6, r = idx & 63; int j = j0 + r;
        if (j < NT)
            y[(size_t)b*NT1 + 1 + j] = (t[r*65 + b] - g_mu[b]) * g_rstd[b] * lng[j] + lnb[j];
    }
    if (blockIdx.x == 0 && tid < B) y[(size_t)tid*NT1] = fc[tid] * 0.01f;
}

// ---------------- K4: sparse GEMM1 + column-sums (one pass over w1) ---------
__global__ void __launch_bounds__(256,2) k4_sparse(const float* __restrict__ w1,
                                                   const float* __restrict__ lng,
                                                   const float* __restrict__ lnb){
    __shared__ float w_t[GRP][256];
    __shared__ float cnt_t[GRP][64];
    __shared__ float gt[GRP], bt[GRP];
    int tid = threadIdx.x, lane = tid & 31, wid = tid >> 5;
    int cbase  = blockIdx.x * 256;
    int jbase0 = blockIdx.y * RPB;
    float acc[8][8];
    #pragma unroll
    for (int i = 0; i < 8; i++)
        #pragma unroll
        for (int u = 0; u < 8; u++) acc[i][u] = 0.0f;
    float sgw[8] = {0,0,0,0,0,0,0,0}, sbw[8] = {0,0,0,0,0,0,0,0};

    for (int ch = 0; ch < RPB/GRP; ch++){
        int jb = jbase0 + ch*GRP;
        #pragma unroll
        for (int i = 0; i < GRP; i++)
            w_t[i][tid] = w1[(size_t)(1 + jb + i)*1024 + cbase + tid];
        #pragma unroll
        for (int i = 0; i < 5; i++){
            int idx = i*256 + tid; int r = idx >> 6, b = idx & 63;
            cnt_t[r][b] = g_counts[(jb + r)*B + b];
        }
        if (tid < GRP){ gt[tid] = lng[jb + tid]; bt[tid] = lnb[jb + tid]; }
        __syncthreads();

        for (int r = 0; r < GRP; r++){
            float gj = gt[r];
            if (wid == 0){
                float bj = bt[r];
                #pragma unroll
                for (int u = 0; u < 8; u++){
                    float w = w_t[r][lane + 32*u];
                    sgw[u] += gj * w; sbw[u] += bj * w;
                }
            }
            float cv[8]; float s = 0.0f;
            #pragma unroll
            for (int i = 0; i < 8; i++){ cv[i] = cnt_t[r][wid*8 + i]; s += cv[i]; }
            if (s != 0.0f){
                float wv[8];
                #pragma unroll
                for (int u = 0; u < 8; u++) wv[u] = w_t[r][lane + 32*u];
                #pragma unroll
                for (int i = 0; i < 8; i++){
                    if (cv[i] != 0.0f){
                        float v = cv[i] * gj;
                        #pragma unroll
                        for (int u = 0; u < 8; u++) acc[i][u] += v * wv[u];
                    }
                }
            }
        }
        __syncthreads();
    }
    #pragma unroll
    for (int i = 0; i < 8; i++)
        #pragma unroll
        for (int u = 0; u < 8; u++)
            g_pacc[(blockIdx.y*64 + wid*8 + i)*1024 + cbase + lane + 32*u] = acc[i][u];
    if (wid == 0){
        #pragma unroll
        for (int u = 0; u < 8; u++){
            g_psgw[blockIdx.y*1024 + cbase + lane + 32*u] = sgw[u];
            g_psbw[blockIdx.y*1024 + cbase + lane + 32*u] = sbw[u];
        }
    }
}

__global__ void k5a_colsum(){
    int k = blockIdx.x*256 + threadIdx.x;
    float s = 0.0f, s2 = 0.0f;
    #pragma unroll 8
    for (int rc = 0; rc < RC; rc++){ s += g_psgw[rc*1024 + k]; s2 += g_psbw[rc*1024 + k]; }
    g_sgw[k] = s; g_sbw[k] = s2;
}

__global__ void k5_fin(const float* __restrict__ w1, const float* __restrict__ b1,
                       const float* __restrict__ fc){
    int b = blockIdx.y;
    int k = blockIdx.x*256 + threadIdx.x;
    float s = 0.0f;
    #pragma unroll 8
    for (int rc = 0; rc < RC; rc++) s += g_pacc[rc*(B*H4) + b*1024 + k];
    float logit = fc[b]*0.01f * w1[k] + g_sbw[k]
                - g_mu[b]*g_rstd[b]*g_sgw[k] + g_rstd[b]*s + b1[k];
    g_h1[b*1024 + k] = gelu_exact(logit);
}

// ---------------- K6: LayerNorm(1024) ---------------------------------------
__global__ void k6_ln(const float* __restrict__ g2, const float* __restrict__ b2){
    __shared__ float r1[256], r2[256];
    int b = blockIdx.x, tid = threadIdx.x;
    float v[4]; float s = 0.0f, sq = 0.0f;
    #pragma unroll
    for (int i = 0; i < 4; i++){
        v[i] = g_h1[b*1024 + tid + 256*i];
        s += v[i]; sq += v[i]*v[i];
    }
    r1[tid] = s; r2[tid] = sq; __syncthreads();
    for (int o = 128; o > 0; o >>= 1){
        if (tid < o){ r1[tid] += r1[tid+o]; r2[tid] += r2[tid+o]; }
        __syncthreads();
    }
    float mu = r1[0] * (1.0f/1024.0f);
    float var = r2[0] * (1.0f/1024.0f) - mu*mu;
    float rs = rsqrtf(var + 1e-5f);
    #pragma unroll
    for (int i = 0; i < 4; i++){
        int k = tid + 256*i;
        g_h2[b*1024 + k] = (v[i] - mu)*rs*g2[k] + b2[k];
    }
}

// ---------------- small GEMM: split-K partial + reduce ----------------------
template<int K, int N, int KPER>
__global__ void __launch_bounds__(256) sg_part(const float* __restrict__ A,
                                               const float* __restrict__ W,
                                               float* __restrict__ P){
    __shared__ float a_s[64*32];
    __shared__ float w_s[32*64];
    int tid = threadIdx.x, lane = tid & 31, wid = tid >> 5;
    int cbase = blockIdx.x*64, kbase = blockIdx.y*KPER;
    float acc[8][2] = {};
    for (int kc = kbase; kc < kbase + KPER; kc += 32){
        #pragma unroll
        for (int i = 0; i < 8; i++){
            int idx = i*256 + tid; int b = idx >> 5, kk = idx & 31;
            a_s[b*32 + kk] = A[b*K + kc + kk];
        }
        #pragma unroll
        for (int i = 0; i < 8; i++){
            int idx = i*256 + tid; int kk = idx >> 6, c = idx & 63;
            w_s[kk*64 + c] = W[(size_t)(kc + kk)*N + cbase + c];
        }
        __syncthreads();
        #pragma unroll
        for (int kk = 0; kk < 32; kk++){
            float av[8], wv0, wv1;
            #pragma unroll
            for (int i = 0; i < 8; i++) av[i] = a_s[(wid*8 + i)*32 + kk];
            wv0 = w_s[kk*64 + lane]; wv1 = w_s[kk*64 + lane + 32];
            #pragma unroll
            for (int i = 0; i < 8; i++){
                acc[i][0] += av[i]*wv0;
                acc[i][1] += av[i]*wv1;
            }
        }
        __syncthreads();
    }
    #pragma unroll
    for (int i = 0; i < 8; i++){
        P[blockIdx.y*(64*N) + (wid*8 + i)*N + cbase + lane]      = acc[i][0];
        P[blockIdx.y*(64*N) + (wid*8 + i)*N + cbase + lane + 32] = acc[i][1];
    }
}

template<int S, int N, bool ACT>
__global__ void sg_reduce(const float* __restrict__ P, const float* __restrict__ bias,
                          float* __restrict__ out, float* __restrict__ out2){
    int i = blockIdx.x*256 + threadIdx.x;
    if (i >= 64*N) return;
    float s = bias[i % N];
    #pragma unroll
    for (int p = 0; p < S; p++) s += P[p*64*N + i];
    if (ACT) s = gelu_exact(s);
    out[i] = s;
    if (out2) out2[i] = s;
}

// ---------------- K10: decoder GEMM [64x1024]@[1024x20001], FFMA2 -----------
// Block: 64 batches x 128 cols, split-K=4 (K=256 each). 8b x 4c per thread.
__global__ void __launch_bounds__(256,2) k10_part(const float* __restrict__ wd2,
                                                  float* __restrict__ P){
    __shared__ __align__(16) float d_s[B*32];
    __shared__ __align__(16) float w_s[128*34];
    int tid = threadIdx.x, lane = tid & 31, wid = tid >> 5;
    int cbase = blockIdx.x * 128;
    int kbase = blockIdx.y * 256;
    unsigned long long acc[32];
    #pragma unroll
    for (int i = 0; i < 32; i++) acc[i] = 0ull;

    for (int kc0 = kbase; kc0 < kbase + 256; kc0 += 32){
        #pragma unroll
        for (int i = 0; i < 8; i++){
            int idx = i*256 + tid; int b = idx >> 5, kk = idx & 31;
            d_s[b*32 + kk] = g_dd[b*1024 + kc0 + kk];
        }
        #pragma unroll
        for (int i = 0; i < 16; i++){
            int idx = i*256 + tid; int kk = idx >> 7, c = idx & 127;
            int gc = cbase + c;
            float v = (gc < NT1) ? wd2[(size_t)(kc0 + kk)*NT1 + gc] : 0.0f;
            w_s[c*34 + kk] = v;
        }
        __syncthreads();
        #pragma unroll
        for (int kp = 0; kp < 16; kp++){
            unsigned long long d2[8], w2[4];
            #pragma unroll
            for (int i = 0; i < 8; i++)
                d2[i] = *(const unsigned long long*)&d_s[(wid*8 + i)*32 + 2*kp];
            #pragma unroll
            for (int u = 0; u < 4; u++)
                w2[u] = *(const unsigned long long*)&w_s[(lane + 32*u)*34 + 2*kp];
            #pragma unroll
            for (int i = 0; i < 8; i++)
                #pragma unroll
                for (int u = 0; u < 4; u++)
                    asm("fma.rn.f32x2 %0, %1, %2, %0;"
                        : "+l"(acc[i*4 + u]) : "l"(d2[i]), "l"(w2[u]));
        }
        __syncthreads();
    }
    #pragma unroll
    for (int i = 0; i < 8; i++)
        #pragma unroll
        for (int u = 0; u < 4; u++){
            int gc = cbase + lane + 32*u;
            if (gc < NT1){
                float lo, hi;
                asm("mov.b64 {%0,%1}, %2;" : "=f"(lo), "=f"(hi) : "l"(acc[i*4 + u]));
                P[(size_t)blockIdx.y*(B*NT1) + (size_t)(wid*8 + i)*NT1 + gc] = lo + hi;
            }
        }
}

__global__ void k10_reduce(const float* __restrict__ P, const float* __restrict__ bd2,
                           float* __restrict__ dec){
    int i = blockIdx.x*256 + threadIdx.x;
    if (i >= B*NT1) return;
    int c = i % NT1;
    float s = bd2[c];
    #pragma unroll
    for (int p = 0; p < 4; p++) s += P[(size_t)p*(B*NT1) + i];
    dec[i] = s;
}

// ---------------- launch -----------------------------------------------------
extern "C" void kernel_launch(void* const* d_in, const int* in_sizes, int n_in,
                              void* d_out, int out_size){
    const int*   tags = (const int*)  d_in[0];
    const float* fc   = (const float*)d_in[1];
    const float* lng  = (const float*)d_in[2];
    const float* lnb  = (const float*)d_in[3];
    const float* w1   = (const float*)d_in[4];
    const float* b1   = (const float*)d_in[5];
    const float* ln2g = (const float*)d_in[6];
    const float* ln2b = (const float*)d_in[7];
    const float* we1  = (const float*)d_in[8];
    const float* be1  = (const float*)d_in[9];
    const float* we2  = (const float*)d_in[10];
    const float* be2  = (const float*)d_in[11];
    const float* wd1  = (const float*)d_in[12];
    const float* bd1  = (const float*)d_in[13];
    const float* wd2  = (const float*)d_in[14];
    const float* bd2  = (const float*)d_in[15];
    float* out = (float*)d_out;

    float *p_h2, *p_h3, *p_enc, *p_dd, *p_pbuf, *p_pacc;
    cudaGetSymbolAddress((void**)&p_h2,   g_h2);
    cudaGetSymbolAddress((void**)&p_h3,   g_h3);
    cudaGetSymbolAddress((void**)&p_enc,  g_encb);
    cudaGetSymbolAddress((void**)&p_dd,   g_dd);
    cudaGetSymbolAddress((void**)&p_pbuf, g_pbuf);
    cudaGetSymbolAddress((void**)&p_pacc, g_pacc);

    k0_zero<<<640, 256>>>();
    k1_scatter<<<32, 256>>>(tags);
    k2a_stats<<<160, 256>>>();
    k2b_fin<<<1, 64>>>();
    k3_y<<<313, 256>>>(fc, lng, lnb, out);
    k4_sparse<<<dim3(4, 40), 256>>>(w1, lng, lnb);
    k5a_colsum<<<4, 256>>>();
    k5_fin<<<dim3(4, 64), 256>>>(w1, b1, fc);
    k6_ln<<<64, 256>>>(ln2g, ln2b);

    // h2 @ we1 (1024->1024) + gelu
    sg_part<1024, 1024, 128><<<dim3(16, 8), 256>>>(p_h2, we1, p_pbuf);
    sg_reduce<8, 1024, true><<<256, 256>>>(p_pbuf, be1, p_h3, (float*)0);
    // h3 @ we2 (1024->256) -> enc (output #2)
    sg_part<1024, 256, 128><<<dim3(4, 8), 256>>>(p_h3, we2, p_pbuf);
    sg_reduce<8, 256, false><<<64, 256>>>(p_pbuf, be2, out + ENC_OFF, p_enc);
    // enc @ wd1 (256->1024) + gelu
    sg_part<256, 1024, 128><<<dim3(16, 2), 256>>>(p_enc, wd1, p_pbuf);
    sg_reduce<2, 1024, true><<<256, 256>>>(p_pbuf, bd1, p_dd, (float*)0);

    // dd @ wd2 (1024->20001) -> dec (output #3)
    k10_part<<<dim3(157, 4), 256>>>(wd2, p_pacc);
    k10_reduce<<<5001, 256>>>(p_pacc, bd2, out + DEC_OFF);
}

// round 5
// speedup vs baseline: 1.1570x; 1.1570x over previous
#include <cuda_runtime.h>
#include <cuda_bf16.h>
#include <math.h>

#define B   64
#define NT  20000
#define NT1 20001
#define H4  1024
#define HD  256
#define Y_SZ    (B*NT1)
#define ENC_OFF Y_SZ
#define DEC_OFF (Y_SZ + B*HD)

// k4 sparse GEMM config
#define RC2  50      // row-chunk blocks in y
#define RPB2 400     // rows per block
#define G4   16      // rows per pipelined chunk
#define NCH4 25      // chunks per block

// ---------------- scratch (device globals; no allocations) -----------------
__device__ float g_counts[NT*B];                 // [tag][batch]
__device__ int   g_istat[128];                   // [0:64) sum, [64:128) sumsq
__device__ float g_mu[B], g_rstd[B];
__device__ float g_pacc[4*B*NT1];                // k4 partials (50*64*1024) & dec split-K partials
__device__ float g_psgw[64*H4], g_psbw[64*H4];
__device__ float g_sgw[H4], g_sbw[H4];
__device__ float g_h1[B*H4], g_h2[B*H4], g_h3[B*H4], g_encb[B*HD], g_dd[B*H4];
__device__ float g_pbuf[32*B*H4];                // small-GEMM split-K partials

__device__ __forceinline__ float gelu_exact(float x){
    return 0.5f * x * (1.0f + erff(x * 0.70710678118654752f));
}
__device__ __forceinline__ void cpa16(void* d, const void* s){
    unsigned a = (unsigned)__cvta_generic_to_shared(d);
    asm volatile("cp.async.ca.shared.global [%0], [%1], 16;" :: "r"(a), "l"(s));
}
__device__ __forceinline__ void cpa4(void* d, const void* s){
    unsigned a = (unsigned)__cvta_generic_to_shared(d);
    asm volatile("cp.async.ca.shared.global [%0], [%1], 4;" :: "r"(a), "l"(s));
}
#define CP_COMMIT() asm volatile("cp.async.commit_group;" ::: "memory")
#define CP_WAIT0()  asm volatile("cp.async.wait_group 0;" ::: "memory")
#define FMA2(a,x,y) asm("fma.rn.f32x2 %0, %1, %2, %0;" : "+l"(a) : "l"(x), "l"(y))

// ---------------- K1: scatter multi-hot counts ------------------------------
__global__ void k1_scatter(const int* __restrict__ tags){
    int p = blockIdx.x*256 + threadIdx.x;       // (b,f) pair, 8192 total
    if (p >= B*128) return;
    int b = p >> 7;
    const int* t = tags + p*16;
    int v[16];
    #pragma unroll
    for (int i = 0; i < 16; i++) v[i] = t[i];
    #pragma unroll
    for (int i = 0; i < 16; i++){
        bool dup = false;
        #pragma unroll
        for (int s = 0; s < 16; s++) if (s < i) dup = dup || (v[s] == v[i]);
        if (!dup) atomicAdd(&g_counts[v[i]*B + b], 1.0f);
    }
}

// ---------------- K2: per-batch stats (integer-exact, deterministic) --------
__global__ void k2a_stats(){
    int tid = threadIdx.x;
    int b = tid & 63;
    int s = 0, sq = 0;
    for (int idx = blockIdx.x*256 + tid; idx < NT*B; idx += 160*256){
        int c = __float2int_rn(g_counts[idx]);
        s += c; sq += c*c;
    }
    atomicAdd(&g_istat[b], s);
    atomicAdd(&g_istat[64 + b], sq);
}
__global__ void k2b_fin(){
    int b = threadIdx.x;
    if (b >= B) return;
    float mu  = (float)g_istat[b] / (float)NT;
    float var = (float)g_istat[64 + b] / (float)NT - mu*mu;
    g_mu[b] = mu;
    g_rstd[b] = rsqrtf(var + 1e-5f);
}

// ---------------- K3: write y (output #1) via smem transpose ----------------
__global__ void __launch_bounds__(256) k3_y(const float* __restrict__ fc,
                                            const float* __restrict__ lng,
                                            const float* __restrict__ lnb,
                                            float* __restrict__ y){
    __shared__ float t[64*65];
    int tid = threadIdx.x;
    int j0 = blockIdx.x * 64;
    #pragma unroll
    for (int i = 0; i < 16; i++){
        int idx = i*256 + tid; int r = idx >> 6, b = idx & 63; int j = j0 + r;
        t[r*65 + b] = (j < NT) ? g_counts[j*B + b] : 0.0f;
    }
    __syncthreads();
    #pragma unroll
    for (int i = 0; i < 16; i++){
        int idx = i*256 + tid; int b = idx >> 6, r = idx & 63; int j = j0 + r;
        if (j < NT)
            y[(size_t)b*NT1 + 1 + j] = (t[r*65 + b] - g_mu[b]) * g_rstd[b] * lng[j] + lnb[j];
    }
    if (blockIdx.x == 0 && tid < B) y[(size_t)tid*NT1] = fc[tid] * 0.01f;
}

// ---------------- K4: sparse GEMM1 + column-sums, cp.async pipelined --------
__global__ void __launch_bounds__(256,2) k4_sparse(const float* __restrict__ w1,
                                                   const float* __restrict__ lng,
                                                   const float* __restrict__ lnb){
    __shared__ __align__(16) float w_t[2][G4*256];
    __shared__ float cnt_t[2][G4*64];
    __shared__ float gb[2][2*G4];
    int tid = threadIdx.x, lane = tid & 31, wid = tid >> 5;
    int cbase = blockIdx.x * 256;
    int jbase = blockIdx.y * RPB2;

    float acc[8][8];
    #pragma unroll
    for (int i = 0; i < 8; i++)
        #pragma unroll
        for (int u = 0; u < 8; u++) acc[i][u] = 0.0f;
    float sgw[8] = {0,0,0,0,0,0,0,0}, sbw[8] = {0,0,0,0,0,0,0,0};
    float creg[4]; float greg = 0.0f, breg = 0.0f;

    // prologue: stage chunk 0
    {
        int jb = jbase;
        #pragma unroll
        for (int i = 0; i < 4; i++){
            int idx = i*256 + tid; int r = idx >> 6, grp = idx & 63;
            cpa16(&w_t[0][r*256 + grp*4], w1 + (size_t)(1 + jb + r)*1024 + cbase + grp*4);
        }
        CP_COMMIT();
        #pragma unroll
        for (int i = 0; i < 4; i++){
            int idx = i*256 + tid; int r = idx >> 6, b = idx & 63;
            creg[i] = g_counts[(jb + r)*B + b];
        }
        if (tid < G4){ greg = lng[jb + tid]; breg = lnb[jb + tid]; }
        #pragma unroll
        for (int i = 0; i < 4; i++){
            int idx = i*256 + tid; int r = idx >> 6, b = idx & 63;
            cnt_t[0][r*64 + b] = creg[i];
        }
        if (tid < G4){ gb[0][tid] = greg; gb[0][G4 + tid] = breg; }
    }

    for (int ch = 0; ch < NCH4; ch++){
        int cur = ch & 1;
        CP_WAIT0();
        __syncthreads();
        if (ch + 1 < NCH4){
            int jb = jbase + (ch + 1)*G4;
            #pragma unroll
            for (int i = 0; i < 4; i++){
                int idx = i*256 + tid; int r = idx >> 6, grp = idx & 63;
                cpa16(&w_t[cur^1][r*256 + grp*4], w1 + (size_t)(1 + jb + r)*1024 + cbase + grp*4);
            }
            CP_COMMIT();
            #pragma unroll
            for (int i = 0; i < 4; i++){
                int idx = i*256 + tid; int r = idx >> 6, b = idx & 63;
                creg[i] = g_counts[(jb + r)*B + b];
            }
            if (tid < G4){ greg = lng[jb + tid]; breg = lnb[jb + tid]; }
        }
        // compute on cur
        for (int r = 0; r < G4; r++){
            float gj = gb[cur][r];
            if (wid == 0){
                float bj = gb[cur][G4 + r];
                #pragma unroll
                for (int u = 0; u < 8; u++){
                    float w = w_t[cur][r*256 + lane + 32*u];
                    sgw[u] += gj * w; sbw[u] += bj * w;
                }
            }
            float cv[8]; float s = 0.0f;
            #pragma unroll
            for (int i = 0; i < 8; i++){ cv[i] = cnt_t[cur][r*64 + wid*8 + i]; s += cv[i]; }
            if (s != 0.0f){
                float wv[8];
                #pragma unroll
                for (int u = 0; u < 8; u++) wv[u] = w_t[cur][r*256 + lane + 32*u];
                #pragma unroll
                for (int i = 0; i < 8; i++){
                    if (cv[i] != 0.0f){
                        float v = cv[i] * gj;
                        #pragma unroll
                        for (int u = 0; u < 8; u++) acc[i][u] += v * wv[u];
                    }
                }
            }
        }
        if (ch + 1 < NCH4){
            #pragma unroll
            for (int i = 0; i < 4; i++){
                int idx = i*256 + tid; int r = idx >> 6, b = idx & 63;
                cnt_t[cur^1][r*64 + b] = creg[i];
            }
            if (tid < G4){ gb[cur^1][tid] = greg; gb[cur^1][G4 + tid] = breg; }
        }
    }

    #pragma unroll
    for (int i = 0; i < 8; i++)
        #pragma unroll
        for (int u = 0; u < 8; u++)
            g_pacc[(blockIdx.y*64 + wid*8 + i)*1024 + cbase + lane + 32*u] = acc[i][u];
    if (wid == 0){
        #pragma unroll
        for (int u = 0; u < 8; u++){
            g_psgw[blockIdx.y*1024 + cbase + lane + 32*u] = sgw[u];
            g_psbw[blockIdx.y*1024 + cbase + lane + 32*u] = sbw[u];
        }
    }
}

__global__ void k5a_colsum(){
    int k = blockIdx.x*256 + threadIdx.x;
    float s = 0.0f, s2 = 0.0f;
    #pragma unroll 10
    for (int rc = 0; rc < RC2; rc++){ s += g_psgw[rc*1024 + k]; s2 += g_psbw[rc*1024 + k]; }
    g_sgw[k] = s; g_sbw[k] = s2;
}

__global__ void k5_fin(const float* __restrict__ w1, const float* __restrict__ b1,
                       const float* __restrict__ fc){
    int b = blockIdx.y;
    int k = blockIdx.x*256 + threadIdx.x;
    float s = 0.0f;
    #pragma unroll 10
    for (int rc = 0; rc < RC2; rc++) s += g_pacc[rc*(B*H4) + b*1024 + k];
    float logit = fc[b]*0.01f * w1[k] + g_sbw[k]
                - g_mu[b]*g_rstd[b]*g_sgw[k] + g_rstd[b]*s + b1[k];
    g_h1[b*1024 + k] = gelu_exact(logit);
}

// ---------------- K6: LayerNorm(1024) ---------------------------------------
__global__ void k6_ln(const float* __restrict__ g2, const float* __restrict__ b2){
    __shared__ float r1[256], r2[256];
    int b = blockIdx.x, tid = threadIdx.x;
    float v[4]; float s = 0.0f, sq = 0.0f;
    #pragma unroll
    for (int i = 0; i < 4; i++){
        v[i] = g_h1[b*1024 + tid + 256*i];
        s += v[i]; sq += v[i]*v[i];
    }
    r1[tid] = s; r2[tid] = sq; __syncthreads();
    for (int o = 128; o > 0; o >>= 1){
        if (tid < o){ r1[tid] += r1[tid+o]; r2[tid] += r2[tid+o]; }
        __syncthreads();
    }
    float mu = r1[0] * (1.0f/1024.0f);
    float var = r2[0] * (1.0f/1024.0f) - mu*mu;
    float rs = rsqrtf(var + 1e-5f);
    #pragma unroll
    for (int i = 0; i < 4; i++){
        int k = tid + 256*i;
        g_h2[b*1024 + k] = (v[i] - mu)*rs*g2[k] + b2[k];
    }
}

// ---------------- small GEMM: split-K partial + reduce ----------------------
template<int K, int N, int KPER>
__global__ void __launch_bounds__(256) sg_part(const float* __restrict__ A,
                                               const float* __restrict__ W,
                                               float* __restrict__ P){
    __shared__ float a_s[64*32];
    __shared__ float w_s[32*64];
    int tid = threadIdx.x, lane = tid & 31, wid = tid >> 5;
    int cbase = blockIdx.x*64, kbase = blockIdx.y*KPER;
    float acc[8][2] = {};
    for (int kc = kbase; kc < kbase + KPER; kc += 32){
        #pragma unroll
        for (int i = 0; i < 8; i++){
            int idx = i*256 + tid; int b = idx >> 5, kk = idx & 31;
            a_s[b*32 + kk] = A[b*K + kc + kk];
        }
        #pragma unroll
        for (int i = 0; i < 8; i++){
            int idx = i*256 + tid; int kk = idx >> 6, c = idx & 63;
            w_s[kk*64 + c] = W[(size_t)(kc + kk)*N + cbase + c];
        }
        __syncthreads();
        #pragma unroll
        for (int kk = 0; kk < 32; kk++){
            float av[8], wv0, wv1;
            #pragma unroll
            for (int i = 0; i < 8; i++) av[i] = a_s[(wid*8 + i)*32 + kk];
            wv0 = w_s[kk*64 + lane]; wv1 = w_s[kk*64 + lane + 32];
            #pragma unroll
            for (int i = 0; i < 8; i++){
                acc[i][0] += av[i]*wv0;
                acc[i][1] += av[i]*wv1;
            }
        }
        __syncthreads();
    }
    #pragma unroll
    for (int i = 0; i < 8; i++){
        P[blockIdx.y*(64*N) + (wid*8 + i)*N + cbase + lane]      = acc[i][0];
        P[blockIdx.y*(64*N) + (wid*8 + i)*N + cbase + lane + 32] = acc[i][1];
    }
}

template<int S, int N, bool ACT>
__global__ void sg_reduce(const float* __restrict__ P, const float* __restrict__ bias,
                          float* __restrict__ out, float* __restrict__ out2){
    int i = blockIdx.x*256 + threadIdx.x;
    if (i >= 64*N) return;
    float s = bias[i % N];
    #pragma unroll
    for (int p = 0; p < S; p++) s += P[p*64*N + i];
    if (ACT) s = gelu_exact(s);
    out[i] = s;
    if (out2) out2[i] = s;
}

// ---------------- K10: decoder GEMM [64x1024]@[1024x20001] ------------------
// Column-paired FFMA2. Block = 64 batches x 256 cols, split-K=4 (K=256 each).
// w streams via cp.async (4B, NT1 is odd so rows are not 16B aligned),
// d staged duplicated (d,d) so LDS.128 yields packed operands directly.
__global__ void __launch_bounds__(256,2) k10_part(const float* __restrict__ wd2,
                                                  float* __restrict__ P){
    extern __shared__ __align__(16) float dsm[];
    float* w_s  = dsm;          // [2][16*256]
    float* d_sm = dsm + 8192;   // [2][64*32] duplicated
    int tid = threadIdx.x, lane = tid & 31, wid = tid >> 5;
    int cbase = blockIdx.x * 256;
    int kbase = blockIdx.y * 256;

    unsigned long long acc[8][4];
    #pragma unroll
    for (int i = 0; i < 8; i++)
        #pragma unroll
        for (int j = 0; j < 4; j++) acc[i][j] = 0ull;
    float dreg[4];

    // prologue: stage chunk 0
    {
        #pragma unroll
        for (int i = 0; i < 16; i++){
            int idx = i*256 + tid; int r = idx >> 8, c = idx & 255;
            int gc = cbase + c;
            float* dst = w_s + r*256 + c;
            if (gc < NT1) cpa4(dst, wd2 + (size_t)(kbase + r)*NT1 + gc);
            else *dst = 0.0f;
        }
        CP_COMMIT();
        #pragma unroll
        for (int i = 0; i < 4; i++){
            int idx = i*256 + tid; int b = idx >> 4, k = idx & 15;
            dreg[i] = g_dd[b*1024 + kbase + k];
        }
        #pragma unroll
        for (int i = 0; i < 4; i++){
            int idx = i*256 + tid; int b = idx >> 4, k = idx & 15;
            d_sm[b*32 + 2*k] = dreg[i]; d_sm[b*32 + 2*k + 1] = dreg[i];
        }
    }

    for (int ch = 0; ch < 16; ch++){
        int cur = ch & 1;
        CP_WAIT0();
        __syncthreads();
        if (ch + 1 < 16){
            int kpos = kbase + (ch + 1)*16;
            float* wdst = w_s + (cur^1)*4096;
            #pragma unroll
            for (int i = 0; i < 16; i++){
                int idx = i*256 + tid; int r = idx >> 8, c = idx & 255;
                int gc = cbase + c;
                float* dst = wdst + r*256 + c;
                if (gc < NT1) cpa4(dst, wd2 + (size_t)(kpos + r)*NT1 + gc);
                else *dst = 0.0f;
            }
            CP_COMMIT();
            #pragma unroll
            for (int i = 0; i < 4; i++){
                int idx = i*256 + tid; int b = idx >> 4, k = idx & 15;
                dreg[i] = g_dd[b*1024 + kpos + k];
            }
        }
        const float* wb = w_s + cur*4096;
        const float* db = d_sm + cur*2048;
        #pragma unroll
        for (int k2 = 0; k2 < 8; k2++){
            ulonglong2 wA0 = *(const ulonglong2*)(wb + (2*k2)*256 + 4*lane);
            ulonglong2 wA1 = *(const ulonglong2*)(wb + (2*k2)*256 + 4*lane + 128);
            ulonglong2 wB0 = *(const ulonglong2*)(wb + (2*k2+1)*256 + 4*lane);
            ulonglong2 wB1 = *(const ulonglong2*)(wb + (2*k2+1)*256 + 4*lane + 128);
            #pragma unroll
            for (int i = 0; i < 8; i++){
                ulonglong2 dv = *(const ulonglong2*)(db + (wid*8 + i)*32 + 4*k2);
                FMA2(acc[i][0], dv.x, wA0.x); FMA2(acc[i][1], dv.x, wA0.y);
                FMA2(acc[i][2], dv.x, wA1.x); FMA2(acc[i][3], dv.x, wA1.y);
                FMA2(acc[i][0], dv.y, wB0.x); FMA2(acc[i][1], dv.y, wB0.y);
                FMA2(acc[i][2], dv.y, wB1.x); FMA2(acc[i][3], dv.y, wB1.y);
            }
        }
        if (ch + 1 < 16){
            float* ddst = d_sm + (cur^1)*2048;
            #pragma unroll
            for (int i = 0; i < 4; i++){
                int idx = i*256 + tid; int b = idx >> 4, k = idx & 15;
                ddst[b*32 + 2*k] = dreg[i]; ddst[b*32 + 2*k + 1] = dreg[i];
            }
        }
    }

    size_t obase = (size_t)blockIdx.y * (B*NT1);
    #pragma unroll
    for (int i = 0; i < 8; i++){
        float* rowp = P + obase + (size_t)(wid*8 + i)*NT1;
        #pragma unroll
        for (int j = 0; j < 4; j++){
            int c = cbase + (j >> 1)*128 + 4*lane + (j & 1)*2;
            float lo, hi;
            asm("mov.b64 {%0,%1}, %2;" : "=f"(lo), "=f"(hi) : "l"(acc[i][j]));
            if (c < NT1)     rowp[c]     = lo;
            if (c + 1 < NT1) rowp[c + 1] = hi;
        }
    }
}

__global__ void k10_reduce(const float* __restrict__ P, const float* __restrict__ bd2,
                           float* __restrict__ dec){
    int i = blockIdx.x*256 + threadIdx.x;
    if (i >= B*NT1) return;
    int c = i % NT1;
    float s = bd2[c];
    #pragma unroll
    for (int p = 0; p < 4; p++) s += P[(size_t)p*(B*NT1) + i];
    dec[i] = s;
}

// ---------------- launch -----------------------------------------------------
extern "C" void kernel_launch(void* const* d_in, const int* in_sizes, int n_in,
                              void* d_out, int out_size){
    const int*   tags = (const int*)  d_in[0];
    const float* fc   = (const float*)d_in[1];
    const float* lng  = (const float*)d_in[2];
    const float* lnb  = (const float*)d_in[3];
    const float* w1   = (const float*)d_in[4];
    const float* b1   = (const float*)d_in[5];
    const float* ln2g = (const float*)d_in[6];
    const float* ln2b = (const float*)d_in[7];
    const float* we1  = (const float*)d_in[8];
    const float* be1  = (const float*)d_in[9];
    const float* we2  = (const float*)d_in[10];
    const float* be2  = (const float*)d_in[11];
    const float* wd1  = (const float*)d_in[12];
    const float* bd1  = (const float*)d_in[13];
    const float* wd2  = (const float*)d_in[14];
    const float* bd2  = (const float*)d_in[15];
    float* out = (float*)d_out;

    float *p_counts, *p_h2, *p_h3, *p_enc, *p_dd, *p_pbuf, *p_pacc;
    int* p_istat;
    cudaGetSymbolAddress((void**)&p_counts, g_counts);
    cudaGetSymbolAddress((void**)&p_istat,  g_istat);
    cudaGetSymbolAddress((void**)&p_h2,     g_h2);
    cudaGetSymbolAddress((void**)&p_h3,     g_h3);
    cudaGetSymbolAddress((void**)&p_enc,    g_encb);
    cudaGetSymbolAddress((void**)&p_dd,     g_dd);
    cudaGetSymbolAddress((void**)&p_pbuf,   g_pbuf);
    cudaGetSymbolAddress((void**)&p_pacc,   g_pacc);

    static int smem_set = 0;
    if (!smem_set){
        cudaFuncSetAttribute(k10_part, cudaFuncAttributeMaxDynamicSharedMemorySize, 49152);
        smem_set = 1;
    }

    cudaMemsetAsync(p_counts, 0, (size_t)NT*B*sizeof(float));
    cudaMemsetAsync(p_istat,  0, 128*sizeof(int));
    k1_scatter<<<32, 256>>>(tags);
    k2a_stats<<<160, 256>>>();
    k2b_fin<<<1, 64>>>();
    k3_y<<<313, 256>>>(fc, lng, lnb, out);
    k4_sparse<<<dim3(4, RC2), 256>>>(w1, lng, lnb);
    k5a_colsum<<<4, 256>>>();
    k5_fin<<<dim3(4, 64), 256>>>(w1, b1, fc);
    k6_ln<<<64, 256>>>(ln2g, ln2b);

    // h2 @ we1 (1024->1024) + gelu
    sg_part<1024, 1024, 32><<<dim3(16, 32), 256>>>(p_h2, we1, p_pbuf);
    sg_reduce<32, 1024, true><<<256, 256>>>(p_pbuf, be1, p_h3, (float*)0);
    // h3 @ we2 (1024->256) -> enc (output #2)
    sg_part<1024, 256, 32><<<dim3(4, 32), 256>>>(p_h3, we2, p_pbuf);
    sg_reduce<32, 256, false><<<64, 256>>>(p_pbuf, be2, out + ENC_OFF, p_enc);
    // enc @ wd1 (256->1024) + gelu
    sg_part<256, 1024, 32><<<dim3(16, 8), 256>>>(p_enc, wd1, p_pbuf);
    sg_reduce<8, 1024, true><<<256, 256>>>(p_pbuf, bd1, p_dd, (float*)0);

    // dd @ wd2 (1024->20001) -> dec (output #3)
    k10_part<<<dim3(79, 4), 256, 49152>>>(wd2, p_pacc);
    k10_reduce<<<5001, 256>>>(p_pacc, bd2, out + DEC_OFF);
}